// round 12
// baseline (speedup 1.0000x reference)
#include <cuda_runtime.h>
#include <math.h>
#include <float.h>

#define NPTS 4096
#define NSAMP 8

// ---- k1 tiling ----
#define JC 8                        // j-chunks (split-K of the softmax)
#define CHUNK (NPTS / JC)           // 512
#define K1_BD 128                   // threads per CTA
#define ROWS_PER 2                  // rows (queries) per thread
#define ROWS_CTA (K1_BD * ROWS_PER) // 256
#define RC_PER_SAMPLE (NPTS / ROWS_CTA) // 16
#define BLK 8                       // j-block cached in registers

#define LN2   0.69314718056f
#define HLN2  0.34657359028f
#define UMIN  3.4657359e-6f         // 0.5*ln2 * EPS (d clipped at 1e-5)

#define NSLICE 16                   // 256-pt slices per sample (stats/accum)

// ---------------- scratch (device globals: no allocations allowed) ----------
__device__ float g_part[NSAMP * JC * 5 * NPTS]; // per-chunk (m,l,a0,a1,a2)
__device__ float g_pcn[NSAMP * 3 * NPTS];       // pc_nearest rows 0..2
__device__ float g_dist[NSAMP * NPTS];          // |pc1 - pcn|
__device__ float g_red13[NSAMP * NSLICE * 13];  // per-slice stats partials
__device__ float g_S4[NSAMP * NSLICE * 40];     // per-slice aa^T partials
__device__ float g_stats[NSAMP * 12];           // mu1,sg1,mu2,sg2

__device__ __forceinline__ float fast_rcp(float x) {
    float r; asm("rcp.approx.f32 %0, %1;" : "=f"(r) : "f"(x)); return r;
}
__device__ __forceinline__ float fast_ex2(float x) {
    float r; asm("ex2.approx.f32 %0, %1;" : "=f"(r) : "f"(x)); return r;
}
// a + b as FFMA with immediate 1.0 multiplier: lands on the fma pipe and the
// FFMA-imm form issues at rt_SMSP=1 (2x FADD's alu-pipe rate).
__device__ __forceinline__ float fadd_fma(float a, float b) {
    float d; asm("fma.rn.f32 %0, %1, 0f3F800000, %2;" : "=f"(d) : "f"(a), "f"(b));
    return d;
}

// ---------------- kernel 1a: block two-pass softmax partial -----------------
// score s = FACT/clip(d,EPS); sb = s*log2(e) = rcp(0.5*ln2*d). Per 8-j block:
// dots once into registers, raise running max m from the block min-u (rcp
// monotone; clamped at block level), rescale accumulators once, then
// accumulate e = ex2(rcp(u) - m) re-reading sh (LDS not binding — measured;
// keeps regs low for occupancy). No per-element clamp: all d >> EPS here so
// reference clip is identity; block-level clamp on m is the safety net.
__global__ void __launch_bounds__(K1_BD) k1_partial(
        const float* __restrict__ pc1, const float* __restrict__ pc2) {
    __shared__ float4 sh[CHUNK];   // 8KB
    int blk = blockIdx.x;
    int jc = blk & (JC - 1);
    int rc = (blk >> 3) & (RC_PER_SAMPLE - 1);
    int b  = blk >> 7;

    const float* p2 = pc2 + b * 4 * NPTS + jc * CHUNK;
    for (int i = threadIdx.x; i < CHUNK; i += K1_BD) {
        float x = p2[i], y = p2[NPTS + i], z = p2[2 * NPTS + i];
        sh[i] = make_float4(x, y, z, HLN2 * (x * x + y * y + z * z));
    }
    __syncthreads();

    const float* p1 = pc1 + b * 4 * NPTS;
    int n0 = rc * ROWS_CTA + threadIdx.x;
    int n1 = n0 + K1_BD;

    float x0 = p1[n0], y0 = p1[NPTS + n0], z0 = p1[2 * NPTS + n0];
    float x1 = p1[n1], y1 = p1[NPTS + n1], z1 = p1[2 * NPTS + n1];
    float C0 = HLN2 * (x0 * x0 + y0 * y0 + z0 * z0);
    float C1 = HLN2 * (x1 * x1 + y1 * y1 + z1 * z1);
    float qx0 = LN2 * x0, qy0 = LN2 * y0, qz0 = LN2 * z0;
    float qx1 = LN2 * x1, qy1 = LN2 * y1, qz1 = LN2 * z1;

    float m0 = -FLT_MAX, l0 = 0.f, ax0 = 0.f, ay0 = 0.f, az0 = 0.f;
    float m1 = -FLT_MAX, l1 = 0.f, ax1 = 0.f, ay1 = 0.f, az1 = 0.f;
    float negm0 = FLT_MAX, negm1 = FLT_MAX;

    for (int jb = 0; jb < CHUNK; jb += BLK) {
        // ---- pass A: dots into registers ----
        float u0[BLK], u1[BLK];
        #pragma unroll
        for (int t = 0; t < BLK; ++t) {
            float4 c = sh[jb + t];
            float a = fadd_fma(c.w, C0);
            a = fmaf(-qx0, c.x, a);
            a = fmaf(-qy0, c.y, a);
            a = fmaf(-qz0, c.z, a);
            u0[t] = a;
            float d = fadd_fma(c.w, C1);
            d = fmaf(-qx1, c.x, d);
            d = fmaf(-qy1, c.y, d);
            d = fmaf(-qz1, c.z, d);
            u1[t] = d;
        }
        // ---- block min (alu pipe) and running-max raise ----
        float mn0 = fminf(fminf(fminf(u0[0], u0[1]), fminf(u0[2], u0[3])),
                          fminf(fminf(u0[4], u0[5]), fminf(u0[6], u0[7])));
        float mn1 = fminf(fminf(fminf(u1[0], u1[1]), fminf(u1[2], u1[3])),
                          fminf(fminf(u1[4], u1[5]), fminf(u1[6], u1[7])));
        float sbm0 = fast_rcp(fmaxf(mn0, UMIN));
        float nm0 = fmaxf(m0, sbm0);
        float sc0 = fast_ex2(m0 - nm0);      // ==1 when max unchanged; 0 first block
        m0 = nm0; negm0 = -nm0;
        l0 *= sc0; ax0 *= sc0; ay0 *= sc0; az0 *= sc0;

        float sbm1 = fast_rcp(fmaxf(mn1, UMIN));
        float nm1 = fmaxf(m1, sbm1);
        float sc1 = fast_ex2(m1 - nm1);
        m1 = nm1; negm1 = -nm1;
        l1 *= sc1; ax1 *= sc1; ay1 *= sc1; az1 *= sc1;

        // ---- pass B: accumulate, re-reading sh (keeps registers low) ----
        #pragma unroll
        for (int t = 0; t < BLK; ++t) {
            float4 c = sh[jb + t];
            float e0 = fast_ex2(fadd_fma(fast_rcp(u0[t]), negm0));
            l0 = fadd_fma(e0, l0);
            ax0 = fmaf(e0, c.x, ax0);
            ay0 = fmaf(e0, c.y, ay0);
            az0 = fmaf(e0, c.z, az0);
            float e1 = fast_ex2(fadd_fma(fast_rcp(u1[t]), negm1));
            l1 = fadd_fma(e1, l1);
            ax1 = fmaf(e1, c.x, ax1);
            ay1 = fmaf(e1, c.y, ay1);
            az1 = fmaf(e1, c.z, az1);
        }
    }

    float* bp = g_part + (size_t)(b * JC + jc) * 5 * NPTS;
    bp[0 * NPTS + n0] = m0;  bp[0 * NPTS + n1] = m1;
    bp[1 * NPTS + n0] = l0;  bp[1 * NPTS + n1] = l1;
    bp[2 * NPTS + n0] = ax0; bp[2 * NPTS + n1] = ax1;
    bp[3 * NPTS + n0] = ay0; bp[3 * NPTS + n1] = ay1;
    bp[4 * NPTS + n0] = az0; bp[4 * NPTS + n1] = az1;
}

// ---------------- kernel 1b: merge partials + dist + stats partial sums -----
__device__ __forceinline__ float warp_sum(float v) {
    #pragma unroll
    for (int o = 16; o; o >>= 1) v += __shfl_down_sync(0xffffffffu, v, o);
    return v;
}

// grid = NSAMP*NSLICE = 128 blocks of 256 threads; 1 point/thread.
__global__ void __launch_bounds__(256) k1b_merge_stats(
        const float* __restrict__ pc1) {
    __shared__ float red[13][8];
    int tid = threadIdx.x;
    int lane = tid & 31, w = tid >> 5;
    int idx = blockIdx.x * 256 + tid;
    int b = idx >> 12;
    int n = idx & (NPTS - 1);

    const float* bp = g_part + (size_t)b * JC * 5 * NPTS;
    float mc[JC];
    float M = -FLT_MAX;
#pragma unroll
    for (int c = 0; c < JC; ++c) {
        mc[c] = bp[(c * 5 + 0) * NPTS + n];
        M = fmaxf(M, mc[c]);
    }
    float l = 0.f, ax = 0.f, ay = 0.f, az = 0.f;
#pragma unroll
    for (int c = 0; c < JC; ++c) {
        float f = fast_ex2(mc[c] - M);
        l  = fmaf(bp[(c * 5 + 1) * NPTS + n], f, l);
        ax = fmaf(bp[(c * 5 + 2) * NPTS + n], f, ax);
        ay = fmaf(bp[(c * 5 + 3) * NPTS + n], f, ay);
        az = fmaf(bp[(c * 5 + 4) * NPTS + n], f, az);
    }
    float inv = 1.0f / l;
    float x2 = ax * inv, y2 = ay * inv, z2 = az * inv;
    float* o = g_pcn + (size_t)b * 3 * NPTS + n;
    o[0]        = x2;
    o[NPTS]     = y2;
    o[2 * NPTS] = z2;

    const float* p1 = pc1 + b * 4 * NPTS;
    float x1 = p1[n], y1 = p1[NPTS + n], z1 = p1[2 * NPTS + n];
    float dx = x1 - x2, dy = y1 - y2, dz = z1 - z2;
    float dist = sqrtf(dx * dx + dy * dy + dz * dz);
    g_dist[b * NPTS + n] = dist;

    float vals[13] = {x1, y1, z1, x1 * x1, y1 * y1, z1 * z1,
                      x2, y2, z2, x2 * x2, y2 * y2, z2 * z2, dist};
    #pragma unroll
    for (int k = 0; k < 13; ++k) {
        float v = warp_sum(vals[k]);
        if (lane == 0) red[k][w] = v;
    }
    __syncthreads();
    if (tid < 13) {
        float v = 0.f;
        #pragma unroll
        for (int w2 = 0; w2 < 8; ++w2) v += red[tid][w2];
        g_red13[blockIdx.x * 13 + tid] = v;
    }
}

// ---------------- kernel 2: masked normal-matrix partial sums ---------------
__global__ void __launch_bounds__(256) k2_accum(const float* __restrict__ pc1) {
    __shared__ float sums[13];
    __shared__ float red[40][8];
    int tid = threadIdx.x;
    int lane = tid & 31, w = tid >> 5;
    int b = blockIdx.x >> 4;

    if (tid < 13) {
        float v = 0.f;
        #pragma unroll
        for (int s = 0; s < NSLICE; ++s)
            v += g_red13[(b * NSLICE + s) * 13 + tid];
        sums[tid] = v;
    }
    __syncthreads();

    const float invN = 1.0f / NPTS;
    float mu1[3], isg1[3], mu2[3], isg2[3];
    #pragma unroll
    for (int k = 0; k < 3; ++k) {
        float s = sums[k], q = sums[3 + k];
        mu1[k] = s * invN;
        isg1[k] = 1.0f / sqrtf(fmaxf(0.f, (q - s * s * invN) * (1.0f / (NPTS - 1))));
        s = sums[6 + k]; q = sums[9 + k];
        mu2[k] = s * invN;
        isg2[k] = 1.0f / sqrtf(fmaxf(0.f, (q - s * s * invN) * (1.0f / (NPTS - 1))));
    }
    float thr = sums[12] * invN + 1e-5f;

    int idx = blockIdx.x * 256 + tid;
    int n = idx & (NPTS - 1);
    const float* p1 = pc1 + b * 4 * NPTS;
    const float* pn = g_pcn + (size_t)b * 3 * NPTS;

    float flag = (g_dist[b * NPTS + n] < thr) ? 1.f : 0.f;
    float a0 = (p1[n]        - mu1[0]) * isg1[0];
    float a1 = (p1[NPTS+n]   - mu1[1]) * isg1[1];
    float a2 = (p1[2*NPTS+n] - mu1[2]) * isg1[2];
    float c0 = (pn[n]        - mu2[0]) * isg2[0];
    float c1 = (pn[NPTS+n]   - mu2[1]) * isg2[1];
    float c2 = (pn[2*NPTS+n] - mu2[2]) * isg2[2];
    float aa[10] = {a0*a0, a0*a1, a0*a2, a0,
                    a1*a1, a1*a2, a1,
                    a2*a2, a2, 1.f};
    float w22 = flag * c2 * c2;
    float w02 = flag * c0 * c2;
    float w12 = flag * c1 * c2;
    float w01 = flag * (c0 * c0 + c1 * c1);

    float acc[40];
    #pragma unroll
    for (int k = 0; k < 10; ++k) {
        acc[k]      = w22 * aa[k];
        acc[10 + k] = w02 * aa[k];
        acc[20 + k] = w12 * aa[k];
        acc[30 + k] = w01 * aa[k];
    }
    #pragma unroll
    for (int k = 0; k < 40; ++k) {
        float v = warp_sum(acc[k]);
        if (lane == 0) red[k][w] = v;
    }
    __syncthreads();
    if (tid < 40) {
        float v = 0.f;
        #pragma unroll
        for (int w2 = 0; w2 < 8; ++w2) v += red[tid][w2];
        g_S4[blockIdx.x * 40 + tid] = v;
    }
    if ((blockIdx.x & 15) == 0 && tid == 0) {
        float* st = g_stats + b * 12;
        #pragma unroll
        for (int k = 0; k < 3; ++k) {
            st[k]     = mu1[k];
            st[3 + k] = 1.0f / isg1[k];
            st[6 + k] = mu2[k];
            st[9 + k] = 1.0f / isg2[k];
        }
    }
}

// ---------------- kernel 3: parallel Jacobi (R3 structure, 4 sweeps) --------
__device__ __forceinline__ void rr_pair(int r, int k, int& p, int& q) {
    if (k == 0) { p = 11; q = r; }
    else { p = (r + k) % 11; q = (r - k + 11) % 11; }
}

#define NSWEEP 4
__global__ void __launch_bounds__(192) k3_solve(float* __restrict__ out) {
    __shared__ float S_sh[40];
    __shared__ float A[12][12];
    __shared__ float V[12][12];
    int b = blockIdx.x;
    int tid = threadIdx.x;

    if (tid < 40) {
        float v = 0.f;
        #pragma unroll
        for (int s = 0; s < NSLICE; ++s)
            v += g_S4[(b * NSLICE + s) * 40 + tid];
        S_sh[tid] = v;
    }
    __syncthreads();

    if (tid == 0) {
        const float* S = S_sh;
        const int II[10] = {0,0,0,0,1,1,1,2,2,3};
        const int JJ[10] = {0,1,2,3,1,2,3,2,3,3};
        float M22[4][4], M02[4][4], M12[4][4], M01[4][4];
        for (int k = 0; k < 10; ++k) {
            int i = II[k], j = JJ[k];
            M22[i][j]=M22[j][i]=S[k];
            M02[i][j]=M02[j][i]=S[10+k];
            M12[i][j]=M12[j][i]=S[20+k];
            M01[i][j]=M01[j][i]=S[30+k];
        }
        for (int i = 0; i < 4; ++i)
        for (int j = 0; j < 4; ++j) {
            A[i][j]     = M22[i][j];
            A[4+i][4+j] = M22[i][j];
            A[8+i][8+j] = M01[i][j];
            A[i][4+j] = 0.f; A[4+i][j] = 0.f;
            A[i][8+j]   = -M02[i][j]; A[8+j][i]   = -M02[i][j];
            A[4+i][8+j] = -M12[i][j]; A[8+j][4+i] = -M12[i][j];
        }
    }
    if (tid < 12)
        for (int j = 0; j < 12; ++j) V[tid][j] = (tid == j) ? 1.f : 0.f;
    __syncthreads();

    bool isA = tid < 72;
    bool isV = (tid >= 72) && (tid < 144);
    int t2 = isA ? tid : tid - 72;
    int i6 = t2 / 12, kk = t2 % 12;

    for (int sweep = 0; sweep < NSWEEP; ++sweep) {
        for (int r = 0; r < 11; ++r) {
            float c = 1.f, s = 0.f, e1 = 0.f, e2 = 0.f;
            int p = 0, q = 0;
            if (tid < 144) {
                rr_pair(r, i6, p, q);
                float apq = A[p][q], app = A[p][p], aqq = A[q][q];
                if (apq != 0.f &&
                    fabsf(apq) > 1e-12f * (fabsf(app) + fabsf(aqq))) {
                    float theta = __fdividef(aqq - app, 2.f * apq);
                    float t = __fdividef((theta >= 0.f) ? 1.f : -1.f,
                                         fabsf(theta) + sqrtf(fmaf(theta, theta, 1.f)));
                    c = rsqrtf(fmaf(t, t, 1.f));
                    s = t * c;
                }
                if (isA) { e1 = A[kk][p]; e2 = A[kk][q]; }
                else     { e1 = V[kk][p]; e2 = V[kk][q]; }
            }
            __syncthreads();
            if (isA)      { A[kk][p] = c * e1 - s * e2; A[kk][q] = s * e1 + c * e2; }
            else if (isV) { V[kk][p] = c * e1 - s * e2; V[kk][q] = s * e1 + c * e2; }
            __syncthreads();
            if (isA) {
                float apk = A[p][kk], aqk = A[q][kk];
                A[p][kk] = c * apk - s * aqk;
                A[q][kk] = s * apk + c * aqk;
            }
            __syncthreads();
        }
    }

    if (tid == 0) {
        int kmin = 0; float emin = A[0][0];
        for (int k = 1; k < 12; ++k)
            if (A[k][k] < emin) { emin = A[k][k]; kmin = k; }
        float p[12];
        for (int i = 0; i < 12; ++i) p[i] = V[i][kmin];
        if (p[10] < 0.f) for (int i = 0; i < 12; ++i) p[i] = -p[i];
        float nrm = sqrtf(p[8]*p[8] + p[9]*p[9] + p[10]*p[10]);
        for (int i = 0; i < 12; ++i) p[i] /= nrm;

        const float* st = g_stats + b * 12;
        float T1m[4][4] = {{0}};
        float iT2[4][4] = {{0}};
        for (int i = 0; i < 3; ++i) {
            T1m[i][i] = 1.0f / st[3 + i];
            T1m[i][3] = -st[i] / st[3 + i];
            iT2[i][i] = st[9 + i];
            iT2[i][3] = st[6 + i];
        }
        T1m[3][3] = 1.f; iT2[3][3] = 1.f;

        float Tp[4][4] = {{p[0],p[1],p[2],p[3]},
                          {p[4],p[5],p[6],p[7]},
                          {p[8],p[9],p[10],p[11]},
                          {0.f,0.f,0.f,1.f}};
        float tmp[4][4], T[4][4];
        for (int i = 0; i < 4; ++i)
        for (int j = 0; j < 4; ++j) {
            float v = 0.f;
            for (int k = 0; k < 4; ++k) v = fmaf(Tp[i][k], T1m[k][j], v);
            tmp[i][j] = v;
        }
        for (int i = 0; i < 4; ++i)
        for (int j = 0; j < 4; ++j) {
            float v = 0.f;
            for (int k = 0; k < 4; ++k) v = fmaf(iT2[i][k], tmp[k][j], v);
            T[i][j] = v;
        }

        float zx=T[0][2], zy=T[1][2], zz=T[2][2];
        float zn = sqrtf(zx*zx + zy*zy + zz*zz);
        zx /= zn; zy /= zn; zz /= zn;
        float yx=T[0][1], yy=T[1][1], yz=T[2][1];
        float xx = yy*zz - yz*zy;
        float xy = yz*zx - yx*zz;
        float xz = yx*zy - yy*zx;
        float xn = sqrtf(xx*xx + xy*xy + xz*xz);
        xx /= xn; xy /= xn; xz /= xn;
        yx = zy*xz - zz*xy;
        yy = zz*xx - zx*xz;
        yz = zx*xy - zy*xx;
        float R[3][3] = {{xx, yx, zx},
                         {xy, yy, zy},
                         {xz, yz, zz}};

        float r00=R[0][0], r11=R[1][1], r22=R[2][2];
        float qw = 0.5f * sqrtf(fmaxf(1e-12f, 1.f + r00 + r11 + r22));
        float qx = 0.5f * sqrtf(fmaxf(0.f, 1.f + r00 - r11 - r22));
        float qy = 0.5f * sqrtf(fmaxf(0.f, 1.f - r00 + r11 - r22));
        float qz = 0.5f * sqrtf(fmaxf(0.f, 1.f - r00 - r11 + r22));
        if (R[2][1] - R[1][2] < 0.f) qx = -qx;
        if (R[0][2] - R[2][0] < 0.f) qy = -qy;
        if (R[1][0] - R[0][1] < 0.f) qz = -qz;

        float* oT = out + b * 16;
        for (int i = 0; i < 3; ++i) {
            oT[i*4 + 0] = R[i][0];
            oT[i*4 + 1] = R[i][1];
            oT[i*4 + 2] = R[i][2];
            oT[i*4 + 3] = T[i][3];
        }
        oT[12] = T[3][0]; oT[13] = T[3][1]; oT[14] = T[3][2]; oT[15] = T[3][3];

        float* oq = out + NSAMP * 16 + b * 4;
        oq[0] = qw; oq[1] = qx; oq[2] = qy; oq[3] = qz;

        float* ot = out + NSAMP * 16 + NSAMP * 4 + b * 3;
        ot[0] = T[0][3]; ot[1] = T[1][3]; ot[2] = T[2][3];
    }
}

// ---------------- launch -----------------------------------------------------
extern "C" void kernel_launch(void* const* d_in, const int* in_sizes, int n_in,
                              void* d_out, int out_size) {
    (void)in_sizes; (void)n_in; (void)out_size;
    const float* pc1 = (const float*)d_in[0];
    const float* pc2 = (const float*)d_in[1];
    float* out = (float*)d_out;

    k1_partial<<<NSAMP * RC_PER_SAMPLE * JC, K1_BD>>>(pc1, pc2);
    k1b_merge_stats<<<NSAMP * NSLICE, 256>>>(pc1);
    k2_accum<<<NSAMP * NSLICE, 256>>>(pc1);
    k3_solve<<<NSAMP, 192>>>(out);
}

// round 13
// speedup vs baseline: 1.1408x; 1.1408x over previous
#include <cuda_runtime.h>
#include <math.h>
#include <float.h>

#define NPTS 4096
#define NSAMP 8

// ---- k1 tiling ----
#define JC 8                        // j-chunks (split-K of the softmax)
#define CHUNK (NPTS / JC)           // 512
#define K1_BD 128                   // threads per CTA
#define ROWS_PER 2                  // rows (queries) per thread
#define ROWS_CTA (K1_BD * ROWS_PER) // 256
#define RC_PER_SAMPLE (NPTS / ROWS_CTA) // 16
#define BLK 16                      // j-block per two-pass iteration

#define LN2   0.69314718056f
#define HLN2  0.34657359028f
#define UMIN  3.4657359e-6f         // 0.5*ln2 * EPS (d clipped at 1e-5)

#define NSLICE 16                   // 256-pt slices per sample (stats/accum)

// ---------------- scratch (device globals: no allocations allowed) ----------
__device__ float g_part[NSAMP * JC * 5 * NPTS]; // per-chunk (m,l,a0,a1,a2)
__device__ float g_pcn[NSAMP * 3 * NPTS];       // pc_nearest rows 0..2
__device__ float g_dist[NSAMP * NPTS];          // |pc1 - pcn|
__device__ float g_red13[NSAMP * NSLICE * 13];  // per-slice stats partials
__device__ float g_S4[NSAMP * NSLICE * 40];     // per-slice aa^T partials
__device__ float g_stats[NSAMP * 12];           // mu1,sg1,mu2,sg2

__device__ __forceinline__ float fast_rcp(float x) {
    float r; asm("rcp.approx.f32 %0, %1;" : "=f"(r) : "f"(x)); return r;
}
__device__ __forceinline__ float fast_ex2(float x) {
    float r; asm("ex2.approx.f32 %0, %1;" : "=f"(r) : "f"(x)); return r;
}
// a + b as FFMA with immediate 1.0 multiplier: lands on the fma pipe and the
// FFMA-imm form issues at rt_SMSP=1 (2x FADD's alu-pipe rate).
__device__ __forceinline__ float fadd_fma(float a, float b) {
    float d; asm("fma.rn.f32 %0, %1, 0f3F800000, %2;" : "=f"(d) : "f"(a), "f"(b));
    return d;
}

// ---------------- kernel 1a: block two-pass softmax partial -----------------
// score s = FACT/clip(d,EPS); sb = s*log2(e) = rcp(0.5*ln2*d). Per 16-j block:
// dots once into registers, raise running max m from the block min-u (rcp
// monotone; clamped at block level), rescale accumulators once, then
// accumulate e = ex2(rcp(u) - m) re-reading sh. No per-element clamp: all
// d >> EPS here so reference clip is identity; block-level clamp is the net.
__global__ void __launch_bounds__(K1_BD) k1_partial(
        const float* __restrict__ pc1, const float* __restrict__ pc2) {
    __shared__ float4 sh[CHUNK];   // 8KB
    int blk = blockIdx.x;
    int jc = blk & (JC - 1);
    int rc = (blk >> 3) & (RC_PER_SAMPLE - 1);
    int b  = blk >> 7;

    const float* p2 = pc2 + b * 4 * NPTS + jc * CHUNK;
    for (int i = threadIdx.x; i < CHUNK; i += K1_BD) {
        float x = p2[i], y = p2[NPTS + i], z = p2[2 * NPTS + i];
        sh[i] = make_float4(x, y, z, HLN2 * (x * x + y * y + z * z));
    }
    __syncthreads();

    const float* p1 = pc1 + b * 4 * NPTS;
    int n0 = rc * ROWS_CTA + threadIdx.x;
    int n1 = n0 + K1_BD;

    float x0 = p1[n0], y0 = p1[NPTS + n0], z0 = p1[2 * NPTS + n0];
    float x1 = p1[n1], y1 = p1[NPTS + n1], z1 = p1[2 * NPTS + n1];
    float C0 = HLN2 * (x0 * x0 + y0 * y0 + z0 * z0);
    float C1 = HLN2 * (x1 * x1 + y1 * y1 + z1 * z1);
    float qx0 = LN2 * x0, qy0 = LN2 * y0, qz0 = LN2 * z0;
    float qx1 = LN2 * x1, qy1 = LN2 * y1, qz1 = LN2 * z1;

    float m0 = -FLT_MAX, l0 = 0.f, ax0 = 0.f, ay0 = 0.f, az0 = 0.f;
    float m1 = -FLT_MAX, l1 = 0.f, ax1 = 0.f, ay1 = 0.f, az1 = 0.f;
    float negm0 = FLT_MAX, negm1 = FLT_MAX;

    for (int jb = 0; jb < CHUNK; jb += BLK) {
        // ---- pass A: dots into registers ----
        float u0[BLK], u1[BLK];
        #pragma unroll
        for (int t = 0; t < BLK; ++t) {
            float4 c = sh[jb + t];
            float a = fadd_fma(c.w, C0);
            a = fmaf(-qx0, c.x, a);
            a = fmaf(-qy0, c.y, a);
            a = fmaf(-qz0, c.z, a);
            u0[t] = a;
            float d = fadd_fma(c.w, C1);
            d = fmaf(-qx1, c.x, d);
            d = fmaf(-qy1, c.y, d);
            d = fmaf(-qz1, c.z, d);
            u1[t] = d;
        }
        // ---- block min (alu pipe) and running-max raise ----
        float mn0 = u0[0], mn1 = u1[0];
        #pragma unroll
        for (int t = 1; t < BLK; ++t) {
            mn0 = fminf(mn0, u0[t]);
            mn1 = fminf(mn1, u1[t]);
        }
        float sbm0 = fast_rcp(fmaxf(mn0, UMIN));
        float nm0 = fmaxf(m0, sbm0);
        float sc0 = fast_ex2(m0 - nm0);      // ==1 when max unchanged; 0 first block
        m0 = nm0; negm0 = -nm0;
        l0 *= sc0; ax0 *= sc0; ay0 *= sc0; az0 *= sc0;

        float sbm1 = fast_rcp(fmaxf(mn1, UMIN));
        float nm1 = fmaxf(m1, sbm1);
        float sc1 = fast_ex2(m1 - nm1);
        m1 = nm1; negm1 = -nm1;
        l1 *= sc1; ax1 *= sc1; ay1 *= sc1; az1 *= sc1;

        // ---- pass B: accumulate, re-reading sh (keeps registers low) ----
        #pragma unroll
        for (int t = 0; t < BLK; ++t) {
            float4 c = sh[jb + t];
            float e0 = fast_ex2(fadd_fma(fast_rcp(u0[t]), negm0));
            l0 = fadd_fma(e0, l0);
            ax0 = fmaf(e0, c.x, ax0);
            ay0 = fmaf(e0, c.y, ay0);
            az0 = fmaf(e0, c.z, az0);
            float e1 = fast_ex2(fadd_fma(fast_rcp(u1[t]), negm1));
            l1 = fadd_fma(e1, l1);
            ax1 = fmaf(e1, c.x, ax1);
            ay1 = fmaf(e1, c.y, ay1);
            az1 = fmaf(e1, c.z, az1);
        }
    }

    float* bp = g_part + (size_t)(b * JC + jc) * 5 * NPTS;
    bp[0 * NPTS + n0] = m0;  bp[0 * NPTS + n1] = m1;
    bp[1 * NPTS + n0] = l0;  bp[1 * NPTS + n1] = l1;
    bp[2 * NPTS + n0] = ax0; bp[2 * NPTS + n1] = ax1;
    bp[3 * NPTS + n0] = ay0; bp[3 * NPTS + n1] = ay1;
    bp[4 * NPTS + n0] = az0; bp[4 * NPTS + n1] = az1;
}

// ---------------- kernel 1b: merge partials + dist + stats partial sums -----
__device__ __forceinline__ float warp_sum(float v) {
    #pragma unroll
    for (int o = 16; o; o >>= 1) v += __shfl_down_sync(0xffffffffu, v, o);
    return v;
}

// grid = NSAMP*NSLICE = 128 blocks of 256 threads; 1 point/thread.
__global__ void __launch_bounds__(256) k1b_merge_stats(
        const float* __restrict__ pc1) {
    __shared__ float red[13][8];
    int tid = threadIdx.x;
    int lane = tid & 31, w = tid >> 5;
    int idx = blockIdx.x * 256 + tid;
    int b = idx >> 12;
    int n = idx & (NPTS - 1);

    const float* bp = g_part + (size_t)b * JC * 5 * NPTS;
    float mc[JC];
    float M = -FLT_MAX;
#pragma unroll
    for (int c = 0; c < JC; ++c) {
        mc[c] = bp[(c * 5 + 0) * NPTS + n];
        M = fmaxf(M, mc[c]);
    }
    float l = 0.f, ax = 0.f, ay = 0.f, az = 0.f;
#pragma unroll
    for (int c = 0; c < JC; ++c) {
        float f = fast_ex2(mc[c] - M);
        l  = fmaf(bp[(c * 5 + 1) * NPTS + n], f, l);
        ax = fmaf(bp[(c * 5 + 2) * NPTS + n], f, ax);
        ay = fmaf(bp[(c * 5 + 3) * NPTS + n], f, ay);
        az = fmaf(bp[(c * 5 + 4) * NPTS + n], f, az);
    }
    float inv = 1.0f / l;
    float x2 = ax * inv, y2 = ay * inv, z2 = az * inv;
    float* o = g_pcn + (size_t)b * 3 * NPTS + n;
    o[0]        = x2;
    o[NPTS]     = y2;
    o[2 * NPTS] = z2;

    const float* p1 = pc1 + b * 4 * NPTS;
    float x1 = p1[n], y1 = p1[NPTS + n], z1 = p1[2 * NPTS + n];
    float dx = x1 - x2, dy = y1 - y2, dz = z1 - z2;
    float dist = sqrtf(dx * dx + dy * dy + dz * dz);
    g_dist[b * NPTS + n] = dist;

    float vals[13] = {x1, y1, z1, x1 * x1, y1 * y1, z1 * z1,
                      x2, y2, z2, x2 * x2, y2 * y2, z2 * z2, dist};
    #pragma unroll
    for (int k = 0; k < 13; ++k) {
        float v = warp_sum(vals[k]);
        if (lane == 0) red[k][w] = v;
    }
    __syncthreads();
    if (tid < 13) {
        float v = 0.f;
        #pragma unroll
        for (int w2 = 0; w2 < 8; ++w2) v += red[tid][w2];
        g_red13[blockIdx.x * 13 + tid] = v;
    }
}

// ---------------- kernel 2: masked normal-matrix partial sums ---------------
__global__ void __launch_bounds__(256) k2_accum(const float* __restrict__ pc1) {
    __shared__ float sums[13];
    __shared__ float red[40][8];
    int tid = threadIdx.x;
    int lane = tid & 31, w = tid >> 5;
    int b = blockIdx.x >> 4;

    if (tid < 13) {
        float v = 0.f;
        #pragma unroll
        for (int s = 0; s < NSLICE; ++s)
            v += g_red13[(b * NSLICE + s) * 13 + tid];
        sums[tid] = v;
    }
    __syncthreads();

    const float invN = 1.0f / NPTS;
    float mu1[3], isg1[3], mu2[3], isg2[3];
    #pragma unroll
    for (int k = 0; k < 3; ++k) {
        float s = sums[k], q = sums[3 + k];
        mu1[k] = s * invN;
        isg1[k] = 1.0f / sqrtf(fmaxf(0.f, (q - s * s * invN) * (1.0f / (NPTS - 1))));
        s = sums[6 + k]; q = sums[9 + k];
        mu2[k] = s * invN;
        isg2[k] = 1.0f / sqrtf(fmaxf(0.f, (q - s * s * invN) * (1.0f / (NPTS - 1))));
    }
    float thr = sums[12] * invN + 1e-5f;

    int idx = blockIdx.x * 256 + tid;
    int n = idx & (NPTS - 1);
    const float* p1 = pc1 + b * 4 * NPTS;
    const float* pn = g_pcn + (size_t)b * 3 * NPTS;

    float flag = (g_dist[b * NPTS + n] < thr) ? 1.f : 0.f;
    float a0 = (p1[n]        - mu1[0]) * isg1[0];
    float a1 = (p1[NPTS+n]   - mu1[1]) * isg1[1];
    float a2 = (p1[2*NPTS+n] - mu1[2]) * isg1[2];
    float c0 = (pn[n]        - mu2[0]) * isg2[0];
    float c1 = (pn[NPTS+n]   - mu2[1]) * isg2[1];
    float c2 = (pn[2*NPTS+n] - mu2[2]) * isg2[2];
    float aa[10] = {a0*a0, a0*a1, a0*a2, a0,
                    a1*a1, a1*a2, a1,
                    a2*a2, a2, 1.f};
    float w22 = flag * c2 * c2;
    float w02 = flag * c0 * c2;
    float w12 = flag * c1 * c2;
    float w01 = flag * (c0 * c0 + c1 * c1);

    float acc[40];
    #pragma unroll
    for (int k = 0; k < 10; ++k) {
        acc[k]      = w22 * aa[k];
        acc[10 + k] = w02 * aa[k];
        acc[20 + k] = w12 * aa[k];
        acc[30 + k] = w01 * aa[k];
    }
    #pragma unroll
    for (int k = 0; k < 40; ++k) {
        float v = warp_sum(acc[k]);
        if (lane == 0) red[k][w] = v;
    }
    __syncthreads();
    if (tid < 40) {
        float v = 0.f;
        #pragma unroll
        for (int w2 = 0; w2 < 8; ++w2) v += red[tid][w2];
        g_S4[blockIdx.x * 40 + tid] = v;
    }
    if ((blockIdx.x & 15) == 0 && tid == 0) {
        float* st = g_stats + b * 12;
        #pragma unroll
        for (int k = 0; k < 3; ++k) {
            st[k]     = mu1[k];
            st[3 + k] = 1.0f / isg1[k];
            st[6 + k] = mu2[k];
            st[9 + k] = 1.0f / isg2[k];
        }
    }
}

// ---------------- kernel 3: parallel Jacobi (R3 structure, 3 sweeps) --------
__device__ __forceinline__ void rr_pair(int r, int k, int& p, int& q) {
    if (k == 0) { p = 11; q = r; }
    else { p = (r + k) % 11; q = (r - k + 11) % 11; }
}

#define NSWEEP 3
__global__ void __launch_bounds__(192) k3_solve(float* __restrict__ out) {
    __shared__ float S_sh[40];
    __shared__ float A[12][12];
    __shared__ float V[12][12];
    int b = blockIdx.x;
    int tid = threadIdx.x;

    if (tid < 40) {
        float v = 0.f;
        #pragma unroll
        for (int s = 0; s < NSLICE; ++s)
            v += g_S4[(b * NSLICE + s) * 40 + tid];
        S_sh[tid] = v;
    }
    __syncthreads();

    if (tid == 0) {
        const float* S = S_sh;
        const int II[10] = {0,0,0,0,1,1,1,2,2,3};
        const int JJ[10] = {0,1,2,3,1,2,3,2,3,3};
        float M22[4][4], M02[4][4], M12[4][4], M01[4][4];
        for (int k = 0; k < 10; ++k) {
            int i = II[k], j = JJ[k];
            M22[i][j]=M22[j][i]=S[k];
            M02[i][j]=M02[j][i]=S[10+k];
            M12[i][j]=M12[j][i]=S[20+k];
            M01[i][j]=M01[j][i]=S[30+k];
        }
        for (int i = 0; i < 4; ++i)
        for (int j = 0; j < 4; ++j) {
            A[i][j]     = M22[i][j];
            A[4+i][4+j] = M22[i][j];
            A[8+i][8+j] = M01[i][j];
            A[i][4+j] = 0.f; A[4+i][j] = 0.f;
            A[i][8+j]   = -M02[i][j]; A[8+j][i]   = -M02[i][j];
            A[4+i][8+j] = -M12[i][j]; A[8+j][4+i] = -M12[i][j];
        }
    }
    if (tid < 12)
        for (int j = 0; j < 12; ++j) V[tid][j] = (tid == j) ? 1.f : 0.f;
    __syncthreads();

    bool isA = tid < 72;
    bool isV = (tid >= 72) && (tid < 144);
    int t2 = isA ? tid : tid - 72;
    int i6 = t2 / 12, kk = t2 % 12;

    for (int sweep = 0; sweep < NSWEEP; ++sweep) {
        for (int r = 0; r < 11; ++r) {
            float c = 1.f, s = 0.f, e1 = 0.f, e2 = 0.f;
            int p = 0, q = 0;
            if (tid < 144) {
                rr_pair(r, i6, p, q);
                float apq = A[p][q], app = A[p][p], aqq = A[q][q];
                if (apq != 0.f &&
                    fabsf(apq) > 1e-12f * (fabsf(app) + fabsf(aqq))) {
                    float theta = __fdividef(aqq - app, 2.f * apq);
                    float t = __fdividef((theta >= 0.f) ? 1.f : -1.f,
                                         fabsf(theta) + sqrtf(fmaf(theta, theta, 1.f)));
                    c = rsqrtf(fmaf(t, t, 1.f));
                    s = t * c;
                }
                if (isA) { e1 = A[kk][p]; e2 = A[kk][q]; }
                else     { e1 = V[kk][p]; e2 = V[kk][q]; }
            }
            __syncthreads();
            if (isA)      { A[kk][p] = c * e1 - s * e2; A[kk][q] = s * e1 + c * e2; }
            else if (isV) { V[kk][p] = c * e1 - s * e2; V[kk][q] = s * e1 + c * e2; }
            __syncthreads();
            if (isA) {
                float apk = A[p][kk], aqk = A[q][kk];
                A[p][kk] = c * apk - s * aqk;
                A[q][kk] = s * apk + c * aqk;
            }
            __syncthreads();
        }
    }

    if (tid == 0) {
        int kmin = 0; float emin = A[0][0];
        for (int k = 1; k < 12; ++k)
            if (A[k][k] < emin) { emin = A[k][k]; kmin = k; }
        float p[12];
        for (int i = 0; i < 12; ++i) p[i] = V[i][kmin];
        if (p[10] < 0.f) for (int i = 0; i < 12; ++i) p[i] = -p[i];
        float nrm = sqrtf(p[8]*p[8] + p[9]*p[9] + p[10]*p[10]);
        for (int i = 0; i < 12; ++i) p[i] /= nrm;

        const float* st = g_stats + b * 12;
        float T1m[4][4] = {{0}};
        float iT2[4][4] = {{0}};
        for (int i = 0; i < 3; ++i) {
            T1m[i][i] = 1.0f / st[3 + i];
            T1m[i][3] = -st[i] / st[3 + i];
            iT2[i][i] = st[9 + i];
            iT2[i][3] = st[6 + i];
        }
        T1m[3][3] = 1.f; iT2[3][3] = 1.f;

        float Tp[4][4] = {{p[0],p[1],p[2],p[3]},
                          {p[4],p[5],p[6],p[7]},
                          {p[8],p[9],p[10],p[11]},
                          {0.f,0.f,0.f,1.f}};
        float tmp[4][4], T[4][4];
        for (int i = 0; i < 4; ++i)
        for (int j = 0; j < 4; ++j) {
            float v = 0.f;
            for (int k = 0; k < 4; ++k) v = fmaf(Tp[i][k], T1m[k][j], v);
            tmp[i][j] = v;
        }
        for (int i = 0; i < 4; ++i)
        for (int j = 0; j < 4; ++j) {
            float v = 0.f;
            for (int k = 0; k < 4; ++k) v = fmaf(iT2[i][k], tmp[k][j], v);
            T[i][j] = v;
        }

        float zx=T[0][2], zy=T[1][2], zz=T[2][2];
        float zn = sqrtf(zx*zx + zy*zy + zz*zz);
        zx /= zn; zy /= zn; zz /= zn;
        float yx=T[0][1], yy=T[1][1], yz=T[2][1];
        float xx = yy*zz - yz*zy;
        float xy = yz*zx - yx*zz;
        float xz = yx*zy - yy*zx;
        float xn = sqrtf(xx*xx + xy*xy + xz*xz);
        xx /= xn; xy /= xn; xz /= xn;
        yx = zy*xz - zz*xy;
        yy = zz*xx - zx*xz;
        yz = zx*xy - zy*xx;
        float R[3][3] = {{xx, yx, zx},
                         {xy, yy, zy},
                         {xz, yz, zz}};

        float r00=R[0][0], r11=R[1][1], r22=R[2][2];
        float qw = 0.5f * sqrtf(fmaxf(1e-12f, 1.f + r00 + r11 + r22));
        float qx = 0.5f * sqrtf(fmaxf(0.f, 1.f + r00 - r11 - r22));
        float qy = 0.5f * sqrtf(fmaxf(0.f, 1.f - r00 + r11 - r22));
        float qz = 0.5f * sqrtf(fmaxf(0.f, 1.f - r00 - r11 + r22));
        if (R[2][1] - R[1][2] < 0.f) qx = -qx;
        if (R[0][2] - R[2][0] < 0.f) qy = -qy;
        if (R[1][0] - R[0][1] < 0.f) qz = -qz;

        float* oT = out + b * 16;
        for (int i = 0; i < 3; ++i) {
            oT[i*4 + 0] = R[i][0];
            oT[i*4 + 1] = R[i][1];
            oT[i*4 + 2] = R[i][2];
            oT[i*4 + 3] = T[i][3];
        }
        oT[12] = T[3][0]; oT[13] = T[3][1]; oT[14] = T[3][2]; oT[15] = T[3][3];

        float* oq = out + NSAMP * 16 + b * 4;
        oq[0] = qw; oq[1] = qx; oq[2] = qy; oq[3] = qz;

        float* ot = out + NSAMP * 16 + NSAMP * 4 + b * 3;
        ot[0] = T[0][3]; ot[1] = T[1][3]; ot[2] = T[2][3];
    }
}

// ---------------- launch -----------------------------------------------------
extern "C" void kernel_launch(void* const* d_in, const int* in_sizes, int n_in,
                              void* d_out, int out_size) {
    (void)in_sizes; (void)n_in; (void)out_size;
    const float* pc1 = (const float*)d_in[0];
    const float* pc2 = (const float*)d_in[1];
    float* out = (float*)d_out;

    k1_partial<<<NSAMP * RC_PER_SAMPLE * JC, K1_BD>>>(pc1, pc2);
    k1b_merge_stats<<<NSAMP * NSLICE, 256>>>(pc1);
    k2_accum<<<NSAMP * NSLICE, 256>>>(pc1);
    k3_solve<<<NSAMP, 192>>>(out);
}